// round 8
// baseline (speedup 1.0000x reference)
#include <cuda_runtime.h>
#include <math.h>

#define Bb 8
#define Tt 1024
#define Dd 512
#define Hh 8
#define DHh 64
#define DEPTHL 8
#define FFf 2048
#define NHh 8
#define BSz 64
#define NBk 16
#define NC (NHh*NBk)
#define BHn (Bb*Hh)
#define SEG (NHh*Tt)

// ---------------- scratch (device symbols; addresses resolved on host) ----------------
__device__ float g_x1[Bb*Tt*Dd];
__device__ float g_x2[Bb*Tt*Dd];
__device__ float g_xn[Bb*Tt*Dd];
__device__ float g_qk[Bb*Tt*Dd];
__device__ float g_v [Bb*Tt*Dd];
__device__ float g_ao[Bb*Tt*Dd];
__device__ float g_ffh[Bb*Tt*FFf];
__device__ float g_bo[(size_t)BHn*NHh*Tt*DHh];   // [bh][nh][t][d] (unsorted)
__device__ float g_slog[BHn*NHh*Tt];             // [bh][nh][t]   (unsorted)
__device__ int   g_st [BHn*SEG];
__device__ int   g_bkt[BHn*SEG];
__device__ float g_pool[Bb*Dd];

// ---------------- helpers ----------------
__device__ __forceinline__ float gelu_tanh(float x) {
    float x3 = x*x*x;
    return 0.5f*x*(1.0f + tanhf(0.7978845608028654f*(x + 0.044715f*x3)));
}

__device__ __forceinline__ float blockReduceSum256(float val, float* red) {
    #pragma unroll
    for (int o = 16; o; o >>= 1) val += __shfl_xor_sync(0xffffffffu, val, o);
    int w = threadIdx.x >> 5;
    if ((threadIdx.x & 31) == 0) red[w] = val;
    __syncthreads();
    float r = (threadIdx.x < 8) ? red[threadIdx.x] : 0.f;
    if (threadIdx.x < 32) {
        #pragma unroll
        for (int o = 4; o; o >>= 1) r += __shfl_xor_sync(0xffffffffu, r, o);
        if (threadIdx.x == 0) red[0] = r;
    }
    __syncthreads();
    float out = red[0];
    __syncthreads();
    return out;
}

// ---------------- embedding ----------------
__global__ void embed_kernel(const int* __restrict__ ids,
                             const float* __restrict__ tok,
                             const float* __restrict__ pos,
                             float* __restrict__ x1, float* __restrict__ x2) {
    int i = blockIdx.x*256 + threadIdx.x;
    if (i >= Bb*Tt*Dd) return;
    int d = i & (Dd-1);
    int bt = i >> 9;
    int t = bt & (Tt-1);
    int id = ids[bt];
    if (id < 0) id = 0;
    if (id >= 6400) id = 6399;
    float v = tok[(size_t)id*Dd + d] + pos[t*Dd + d];
    x1[i] = v; x2[i] = v;
}

// ---------------- layernorm (optionally avg of two streams) ----------------
__global__ void ln_kernel(const float* __restrict__ x, const float* __restrict__ xb,
                          float* __restrict__ y,
                          const float* __restrict__ g, const float* __restrict__ bia) {
    __shared__ float red[8];
    int row = blockIdx.x;
    int i0 = row*Dd + threadIdx.x;
    float v0, v1;
    if (xb) { v0 = 0.5f*(x[i0] + xb[i0]); v1 = 0.5f*(x[i0+256] + xb[i0+256]); }
    else    { v0 = x[i0];                 v1 = x[i0+256]; }
    float s = blockReduceSum256(v0+v1, red);
    float mean = s * (1.f/512.f);
    float d0 = v0 - mean, d1 = v1 - mean;
    float s2 = blockReduceSum256(d0*d0 + d1*d1, red);
    float inv = rsqrtf(s2*(1.f/512.f) + 1e-5f);
    y[i0]     = d0*inv*g[threadIdx.x]     + bia[threadIdx.x];
    y[i0+256] = d1*inv*g[threadIdx.x+256] + bia[threadIdx.x+256];
}

// ---------------- generic fp32 GEMM: C = A[MxK] @ B[KxN] ----------------
// EPI: 0 = store, 1 = gelu(acc+bias) store, 3 = C += acc, 4 = C += acc + bias
template<int EPI>
__global__ void gemm_kernel(const float* __restrict__ A, const float* __restrict__ Bm,
                            const float* __restrict__ bias, float* __restrict__ C,
                            int M, int N, int K) {
    __shared__ float As[16][64];
    __shared__ float Bs[16][64];
    int tid = threadIdx.x;
    int bm = blockIdx.y*64, bn = blockIdx.x*64;
    int tx = tid & 15, ty = tid >> 4;
    float acc[4][4];
    #pragma unroll
    for (int i=0;i<4;i++)
        #pragma unroll
        for (int j=0;j<4;j++) acc[i][j]=0.f;

    const float* Ab = A + (size_t)bm*K;
    for (int k0 = 0; k0 < K; k0 += 16) {
        #pragma unroll
        for (int e = 0; e < 4; e++) {
            int idx = tid + e*256;
            int m = idx >> 4, kk = idx & 15;
            As[kk][m] = Ab[(size_t)m*K + k0 + kk];
            int k2 = idx >> 6, n2 = idx & 63;
            Bs[k2][n2] = Bm[(size_t)(k0+k2)*N + bn + n2];
        }
        __syncthreads();
        #pragma unroll
        for (int kk = 0; kk < 16; kk++) {
            float a[4], b[4];
            #pragma unroll
            for (int i=0;i<4;i++) a[i] = As[kk][ty*4+i];
            #pragma unroll
            for (int j=0;j<4;j++) b[j] = Bs[kk][tx*4+j];
            #pragma unroll
            for (int i=0;i<4;i++)
                #pragma unroll
                for (int j=0;j<4;j++) acc[i][j] += a[i]*b[j];
        }
        __syncthreads();
    }
    #pragma unroll
    for (int i=0;i<4;i++) {
        float* Crow = C + (size_t)(bm + ty*4 + i)*N + bn + tx*4;
        #pragma unroll
        for (int j=0;j<4;j++) {
            float v = acc[i][j];
            if (EPI == 1) { v += bias[bn + tx*4 + j]; v = gelu_tanh(v); Crow[j] = v; }
            else if (EPI == 3) { Crow[j] += v; }
            else if (EPI == 4) { Crow[j] += v + bias[bn + tx*4 + j]; }
            else { Crow[j] = v; }
        }
    }
}

// ---------------- LSH hashing: one thread per (bh, nh, t) ----------------
__global__ void hash_kernel(const float* __restrict__ rot,
                            const float* __restrict__ qk, int* __restrict__ bkt) {
    int idx = blockIdx.x*256 + threadIdx.x;
    if (idx >= BHn*NHh*Tt) return;
    int t  = idx & (Tt-1);
    int nh = (idx >> 10) & 7;
    int bh = idx >> 13;
    int b = bh >> 3, h = bh & 7;
    const float* qrow = &qk[(size_t)(b*Tt + t)*Dd + h*DHh];
    float rv[8];
    #pragma unroll
    for (int r = 0; r < 8; r++) rv[r] = 0.f;
    for (int d = 0; d < DHh; d++) {
        float q = qrow[d];
        const float* rp = rot + d*64 + nh*8;    // rot layout [DH][NH][NB/2]
        #pragma unroll
        for (int r = 0; r < 8; r++) rv[r] += q*rp[r];
    }
    int best = 0; float bv = rv[0];
    #pragma unroll
    for (int r = 1; r < 8; r++) if (rv[r] > bv) { bv = rv[r]; best = r; }
    #pragma unroll
    for (int r = 0; r < 8; r++) { float nv = -rv[r]; if (nv > bv) { bv = nv; best = 8 + r; } }
    bkt[(bh*NHh + nh)*Tt + t] = best;
}

// ---------------- stable counting sort, one thread per (bh, nh) segment ----------------
__global__ void sort_kernel(const int* __restrict__ bkt, int* __restrict__ st) {
    int seg = blockIdx.x*64 + threadIdx.x;
    if (seg >= BHn*NHh) return;
    int base = seg*Tt;
    int cnt[16];
    #pragma unroll
    for (int i = 0; i < 16; i++) cnt[i] = 0;
    for (int t = 0; t < Tt; t++) cnt[bkt[base + t]]++;
    int off[16]; int s = 0;
    #pragma unroll
    for (int i = 0; i < 16; i++) { off[i] = s; s += cnt[i]; }
    for (int t = 0; t < Tt; t++) {
        int bb = bkt[base + t];
        st[base + off[bb]++] = t;             // stable: ascending t within bucket
    }
}

// ---------------- chunked LSH attention: one CTA per (chunk, bh) ----------------
__global__ void __launch_bounds__(256) attn_kernel(const int* __restrict__ st,
                                                   const float* __restrict__ qk,
                                                   const float* __restrict__ vg,
                                                   float* __restrict__ slog,
                                                   float* __restrict__ bo) {
    __shared__ float q  [64*65];   // raw qk rows of current chunk (= K half 0)
    __shared__ float buf[64*65];   // streamed K half 1 / V halves
    __shared__ float inv_s[64];
    __shared__ int   posK[128];

    int n = blockIdx.x, bh = blockIdx.y;
    int b = bh >> 3, h = bh & 7;
    int tid = threadIdx.x;
    int nh = n >> 4;               // hash round (16 chunks per round)
    int segb = bh*SEG;

    if (tid < 128) {
        int cc = (tid < 64) ? n : ((n + NC - 1) & (NC-1));
        posK[tid] = st[segb + cc*BSz + (tid & 63)];
    }
    __syncthreads();

    for (int idx = tid; idx < 64*64; idx += 256) {
        int r = idx >> 6, d = idx & 63;
        q[r*65 + d] = qk[(size_t)(b*Tt + posK[r])*Dd + h*DHh + d];
    }

    int r  = tid >> 2;             // query row 0..63
    int c4 = tid & 3;              // key-group lane
    float dots[32];
    int pq;

    // ---- QK^T in two key halves (half 0 keys == q tile itself) ----
    #pragma unroll
    for (int half = 0; half < 2; half++) {
        __syncthreads();
        if (half == 1) {
            for (int idx = tid; idx < 64*64; idx += 256) {
                int rr = idx >> 6, d = idx & 63;
                buf[rr*65 + d] = qk[(size_t)(b*Tt + posK[64 + rr])*Dd + h*DHh + d];
            }
        }
        __syncthreads();
        const float* kb = (half == 0) ? q : buf;
        if (tid < 64) {
            float s = 0.f;
            #pragma unroll
            for (int d = 0; d < 64; d++) { float x = kb[tid*65 + d]; s += x*x; }
            inv_s[tid] = 1.f/(sqrtf(s) + 1e-8f);
        }
        __syncthreads();
        pq = posK[r];
        #pragma unroll
        for (int i = 0; i < 16; i++) {
            int kl = (i << 2) | c4;
            float s = 0.f;
            #pragma unroll
            for (int d = 0; d < 64; d++) s += q[r*65 + d]*kb[kl*65 + d];
            s *= inv_s[kl]*0.125f;                 // unit keys * DH^-0.5
            if (pq == posK[half*64 + kl]) s = -5e4f;
            dots[half*16 + i] = s;
        }
    }

    // ---- softmax across 32 regs + quad (c4) reduce ----
    float mx = -1e30f;
    #pragma unroll
    for (int i = 0; i < 32; i++) mx = fmaxf(mx, dots[i]);
    mx = fmaxf(mx, __shfl_xor_sync(0xffffffffu, mx, 1));
    mx = fmaxf(mx, __shfl_xor_sync(0xffffffffu, mx, 2));
    float se = 0.f;
    #pragma unroll
    for (int i = 0; i < 32; i++) { dots[i] = expf(dots[i] - mx); se += dots[i]; }
    se += __shfl_xor_sync(0xffffffffu, se, 1);
    se += __shfl_xor_sync(0xffffffffu, se, 2);
    if (c4 == 0) slog[((size_t)bh*NHh + nh)*Tt + pq] = mx + logf(se);
    float inv_se = 1.f/se;
    #pragma unroll
    for (int i = 0; i < 32; i++) dots[i] *= inv_se;   // probs

    // ---- PV in two value halves ----
    float acc0[32], acc1[32];
    #pragma unroll
    for (int j = 0; j < 32; j++) { acc0[j] = 0.f; acc1[j] = 0.f; }
    #pragma unroll
    for (int half = 0; half < 2; half++) {
        __syncthreads();
        for (int idx = tid; idx < 64*64; idx += 256) {
            int rr = idx >> 6, d = idx & 63;
            buf[rr*65 + d] = vg[(size_t)(b*Tt + posK[half*64 + rr])*Dd + h*DHh + d];
        }
        __syncthreads();
        #pragma unroll
        for (int i = 0; i < 16; i++) {
            int kl = (i << 2) | c4;
            float p = dots[half*16 + i];
            const float* vr = buf + kl*65;
            #pragma unroll
            for (int j = 0; j < 32; j++) acc0[j] += p*vr[j];
            #pragma unroll
            for (int j = 0; j < 32; j++) acc1[j] += p*vr[32 + j];
        }
    }
    #pragma unroll
    for (int j = 0; j < 32; j++) {
        acc0[j] += __shfl_xor_sync(0xffffffffu, acc0[j], 1);
        acc0[j] += __shfl_xor_sync(0xffffffffu, acc0[j], 2);
        acc1[j] += __shfl_xor_sync(0xffffffffu, acc1[j], 1);
        acc1[j] += __shfl_xor_sync(0xffffffffu, acc1[j], 2);
    }
    if (c4 == 0) {
        float* bop = &bo[(((size_t)bh*NHh + nh)*Tt + pq)*DHh];
        #pragma unroll
        for (int j = 0; j < 32; j++) {
            bop[j]      = acc0[j];
            bop[32 + j] = acc1[j];
        }
    }
}

// ---------------- multi-round logsumexp-weighted combine ----------------
__global__ void combine_kernel(const float* __restrict__ slog,
                               const float* __restrict__ bo,
                               float* __restrict__ ao) {
    int idx = blockIdx.x*256 + threadIdx.x;
    if (idx >= BHn*Tt*DHh) return;
    int d  = idx & 63;
    int t  = (idx >> 6) & (Tt-1);
    int bh = idx >> 16;
    float lg[NHh];
    float mx = -1e30f;
    #pragma unroll
    for (int i = 0; i < NHh; i++) {
        lg[i] = slog[((size_t)bh*NHh + i)*Tt + t];
        mx = fmaxf(mx, lg[i]);
    }
    float se = 0.f;
    #pragma unroll
    for (int i = 0; i < NHh; i++) { lg[i] = expf(lg[i] - mx); se += lg[i]; }
    float inv = 1.f/se;
    float out = 0.f;
    #pragma unroll
    for (int i = 0; i < NHh; i++)
        out += lg[i]*inv * bo[(((size_t)bh*NHh + i)*Tt + t)*DHh + d];
    int b = bh >> 3, h = bh & 7;
    ao[(size_t)(b*Tt + t)*Dd + h*DHh + d] = out;
}

// ---------------- final pooling + fc ----------------
__global__ void pool_kernel(const float* __restrict__ xn, float* __restrict__ pool) {
    int b = blockIdx.x, d = threadIdx.x;
    float s = 0.f;
    for (int t = 0; t < Tt; t++) s += xn[(size_t)(b*Tt + t)*Dd + d];
    pool[b*Dd + d] = s * (1.f/(float)Tt);
}

__global__ void fc_kernel(const float* __restrict__ pool,
                          const float* __restrict__ Wfc, float* __restrict__ out) {
    int b = blockIdx.x, n = threadIdx.x;
    float s = 0.f;
    for (int kk = 0; kk < Dd; kk++) s += pool[b*Dd + kk]*Wfc[kk*Dd + n];
    out[b*Dd + n] = s;
}

// ---------------- orchestration ----------------
extern "C" void kernel_launch(void* const* d_in, const int* in_sizes, int n_in,
                              void* d_out, int out_size) {
    const int*   ids = (const int*)  d_in[0];
    const float* tok = (const float*)d_in[1];
    const float* pos = (const float*)d_in[2];
    const float* lag = (const float*)d_in[3];
    const float* lab = (const float*)d_in[4];
    const float* Wqk = (const float*)d_in[5];
    const float* Wv  = (const float*)d_in[6];
    const float* Wo  = (const float*)d_in[7];
    const float* lfg = (const float*)d_in[8];
    const float* lfb = (const float*)d_in[9];
    const float* W1  = (const float*)d_in[10];
    const float* b1  = (const float*)d_in[11];
    const float* W2  = (const float*)d_in[12];
    const float* b2  = (const float*)d_in[13];
    const float* lng = (const float*)d_in[14];
    const float* lnb = (const float*)d_in[15];
    const float* Wfc = (const float*)d_in[16];
    const float* rot = (const float*)d_in[17];
    float* out = (float*)d_out;

    // *** THE FIX: resolve true device addresses of scratch symbols ***
    float *x1, *x2, *xn, *qk, *v, *ao, *ffh, *bo, *slog, *pool;
    int *st, *bkt;
    cudaGetSymbolAddress((void**)&x1,   g_x1);
    cudaGetSymbolAddress((void**)&x2,   g_x2);
    cudaGetSymbolAddress((void**)&xn,   g_xn);
    cudaGetSymbolAddress((void**)&qk,   g_qk);
    cudaGetSymbolAddress((void**)&v,    g_v);
    cudaGetSymbolAddress((void**)&ao,   g_ao);
    cudaGetSymbolAddress((void**)&ffh,  g_ffh);
    cudaGetSymbolAddress((void**)&bo,   g_bo);
    cudaGetSymbolAddress((void**)&slog, g_slog);
    cudaGetSymbolAddress((void**)&pool, g_pool);
    cudaGetSymbolAddress((void**)&st,   g_st);
    cudaGetSymbolAddress((void**)&bkt,  g_bkt);

    const int M = Bb*Tt;

    embed_kernel<<<(Bb*Tt*Dd + 255)/256, 256>>>(ids, tok, pos, x1, x2);

    for (int l = 0; l < DEPTHL; l++) {
        const float* Wqk_l = Wqk + (size_t)l*Dd*Dd;
        const float* Wv_l  = Wv  + (size_t)l*Dd*Dd;
        const float* Wo_l  = Wo  + (size_t)l*Dd*Dd;
        const float* W1_l  = W1  + (size_t)l*Dd*FFf;
        const float* W2_l  = W2  + (size_t)l*FFf*Dd;
        const float* b1_l  = b1  + (size_t)l*FFf;
        const float* b2_l  = b2  + (size_t)l*Dd;
        const float* rot_l = rot + (size_t)l*DHh*64;

        // attention block: x1 += attn(LN(x2)) @ Wo
        ln_kernel<<<M, 256>>>(x2, nullptr, xn, lag + l*Dd, lab + l*Dd);
        gemm_kernel<0><<<dim3(Dd/64, M/64), 256>>>(xn, Wqk_l, nullptr, qk, M, Dd, Dd);
        gemm_kernel<0><<<dim3(Dd/64, M/64), 256>>>(xn, Wv_l,  nullptr, v,  M, Dd, Dd);
        hash_kernel<<<(BHn*NHh*Tt + 255)/256, 256>>>(rot_l, qk, bkt);
        sort_kernel<<<(BHn*NHh + 63)/64, 64>>>(bkt, st);
        attn_kernel<<<dim3(NC, BHn), 256>>>(st, qk, v, slog, bo);
        combine_kernel<<<(BHn*Tt*DHh + 255)/256, 256>>>(slog, bo, ao);
        gemm_kernel<3><<<dim3(Dd/64, M/64), 256>>>(ao, Wo_l, nullptr, x1, M, Dd, Dd);

        // feed-forward block: x2 += gelu(LN(x1)@W1 + b1) @ W2 + b2
        ln_kernel<<<M, 256>>>(x1, nullptr, xn, lfg + l*Dd, lfb + l*Dd);
        gemm_kernel<1><<<dim3(FFf/64, M/64), 256>>>(xn, W1_l, b1_l, ffh, M, FFf, Dd);
        gemm_kernel<4><<<dim3(Dd/64, M/64), 256>>>(ffh, W2_l, b2_l, x2, M, Dd, FFf);
    }

    // final: 0.5*(x1+x2) -> LN -> mean over T -> @ Wfc
    ln_kernel<<<M, 256>>>(x1, x2, xn, lng, lnb);
    pool_kernel<<<Bb, Dd>>>(xn, pool);
    fc_kernel<<<Bb, Dd>>>(pool, Wfc, out);
}

// round 9
// speedup vs baseline: 2.1313x; 2.1313x over previous
#include <cuda_runtime.h>
#include <math.h>

#define Bb 8
#define Tt 1024
#define Dd 512
#define Hh 8
#define DHh 64
#define DEPTHL 8
#define FFf 2048
#define NHh 8
#define BSz 64
#define NBk 16
#define NC (NHh*NBk)
#define BHn (Bb*Hh)
#define SEG (NHh*Tt)

// ---------------- scratch (device symbols; addresses resolved on host) ----------------
__device__ float g_x1[Bb*Tt*Dd];
__device__ float g_x2[Bb*Tt*Dd];
__device__ float g_xn[Bb*Tt*Dd];
__device__ float g_qk[Bb*Tt*Dd];
__device__ float g_v [Bb*Tt*Dd];
__device__ float g_ao[Bb*Tt*Dd];
__device__ float g_ffh[Bb*Tt*FFf];
__device__ float g_bo[(size_t)BHn*NHh*Tt*DHh];   // [bh][nh][t][d] (unsorted)
__device__ float g_slog[BHn*NHh*Tt];             // [bh][nh][t]   (unsorted)
__device__ int   g_st [BHn*SEG];
__device__ int   g_bkt[BHn*SEG];
__device__ float g_pool[Bb*Dd];

// ---------------- helpers ----------------
__device__ __forceinline__ float gelu_fast(float x) {
    float u = 0.7978845608028654f*(x + 0.044715f*x*x*x);
    float t = 1.f - 2.f/(__expf(2.f*u) + 1.f);       // tanh via fast exp
    return 0.5f*x*(1.f + t);
}

__device__ __forceinline__ float blockReduceSum256(float val, float* red) {
    #pragma unroll
    for (int o = 16; o; o >>= 1) val += __shfl_xor_sync(0xffffffffu, val, o);
    int w = threadIdx.x >> 5;
    if ((threadIdx.x & 31) == 0) red[w] = val;
    __syncthreads();
    float r = (threadIdx.x < 8) ? red[threadIdx.x] : 0.f;
    if (threadIdx.x < 32) {
        #pragma unroll
        for (int o = 4; o; o >>= 1) r += __shfl_xor_sync(0xffffffffu, r, o);
        if (threadIdx.x == 0) red[0] = r;
    }
    __syncthreads();
    float out = red[0];
    __syncthreads();
    return out;
}

// ---------------- embedding ----------------
__global__ void embed_kernel(const int* __restrict__ ids,
                             const float* __restrict__ tok,
                             const float* __restrict__ pos,
                             float* __restrict__ x1, float* __restrict__ x2) {
    int i = blockIdx.x*256 + threadIdx.x;
    if (i >= Bb*Tt*Dd) return;
    int d = i & (Dd-1);
    int bt = i >> 9;
    int t = bt & (Tt-1);
    int id = ids[bt];
    if (id < 0) id = 0;
    if (id >= 6400) id = 6399;
    float v = tok[(size_t)id*Dd + d] + pos[t*Dd + d];
    x1[i] = v; x2[i] = v;
}

// ---------------- layernorm (optionally avg of two streams) ----------------
__global__ void ln_kernel(const float* __restrict__ x, const float* __restrict__ xb,
                          float* __restrict__ y,
                          const float* __restrict__ g, const float* __restrict__ bia) {
    __shared__ float red[8];
    int row = blockIdx.x;
    int i0 = row*Dd + threadIdx.x;
    float v0, v1;
    if (xb) { v0 = 0.5f*(x[i0] + xb[i0]); v1 = 0.5f*(x[i0+256] + xb[i0+256]); }
    else    { v0 = x[i0];                 v1 = x[i0+256]; }
    float s = blockReduceSum256(v0+v1, red);
    float mean = s * (1.f/512.f);
    float d0 = v0 - mean, d1 = v1 - mean;
    float s2 = blockReduceSum256(d0*d0 + d1*d1, red);
    float inv = rsqrtf(s2*(1.f/512.f) + 1e-5f);
    y[i0]     = d0*inv*g[threadIdx.x]     + bia[threadIdx.x];
    y[i0+256] = d1*inv*g[threadIdx.x+256] + bia[threadIdx.x+256];
}

// ---------------- fp32 GEMM 128x128 tile, 8x8 microtile: C = A[MxK] @ B[KxN] ----------------
// EPI: 0 = store, 1 = gelu(acc+bias) store, 3 = C += acc, 4 = C += acc + bias
template<int EPI>
__global__ void __launch_bounds__(256) gemm_kernel(const float* __restrict__ A,
                            const float* __restrict__ Bm,
                            const float* __restrict__ bias, float* __restrict__ C,
                            int M, int N, int K) {
    __shared__ float As[8][128];
    __shared__ float Bs[8][128];
    int tid = threadIdx.x;
    int bm = blockIdx.y*128, bn = blockIdx.x*128;
    int ty = tid >> 4, tx = tid & 15;
    int am = tid >> 1, ak = (tid & 1)*4;
    int bk = tid >> 5, bn4 = (tid & 31)*4;

    float acc[8][8];
    #pragma unroll
    for (int i = 0; i < 8; i++)
        #pragma unroll
        for (int j = 0; j < 8; j++) acc[i][j] = 0.f;

    const float* Aptr = A + (size_t)(bm + am)*K + ak;
    const float* Bptr = Bm + (size_t)bk*N + bn + bn4;

    for (int k0 = 0; k0 < K; k0 += 8) {
        float4 av = *(const float4*)(Aptr + k0);
        float4 bv = *(const float4*)(Bptr + (size_t)k0*N);
        As[ak+0][am] = av.x; As[ak+1][am] = av.y;
        As[ak+2][am] = av.z; As[ak+3][am] = av.w;
        *(float4*)&Bs[bk][bn4] = bv;
        __syncthreads();
        #pragma unroll
        for (int kk = 0; kk < 8; kk++) {
            float a[8], b[8];
            *(float4*)(a)   = *(const float4*)&As[kk][ty*8];
            *(float4*)(a+4) = *(const float4*)&As[kk][ty*8+4];
            *(float4*)(b)   = *(const float4*)&Bs[kk][tx*8];
            *(float4*)(b+4) = *(const float4*)&Bs[kk][tx*8+4];
            #pragma unroll
            for (int i = 0; i < 8; i++)
                #pragma unroll
                for (int j = 0; j < 8; j++) acc[i][j] += a[i]*b[j];
        }
        __syncthreads();
    }

    #pragma unroll
    for (int i = 0; i < 8; i++) {
        float* Crow = C + (size_t)(bm + ty*8 + i)*N + bn + tx*8;
        if (EPI == 0) {
            float4 o0 = make_float4(acc[i][0],acc[i][1],acc[i][2],acc[i][3]);
            float4 o1 = make_float4(acc[i][4],acc[i][5],acc[i][6],acc[i][7]);
            *(float4*)Crow = o0; *(float4*)(Crow+4) = o1;
        } else if (EPI == 1) {
            float4 o0, o1;
            o0.x = gelu_fast(acc[i][0] + bias[bn+tx*8+0]);
            o0.y = gelu_fast(acc[i][1] + bias[bn+tx*8+1]);
            o0.z = gelu_fast(acc[i][2] + bias[bn+tx*8+2]);
            o0.w = gelu_fast(acc[i][3] + bias[bn+tx*8+3]);
            o1.x = gelu_fast(acc[i][4] + bias[bn+tx*8+4]);
            o1.y = gelu_fast(acc[i][5] + bias[bn+tx*8+5]);
            o1.z = gelu_fast(acc[i][6] + bias[bn+tx*8+6]);
            o1.w = gelu_fast(acc[i][7] + bias[bn+tx*8+7]);
            *(float4*)Crow = o0; *(float4*)(Crow+4) = o1;
        } else if (EPI == 3) {
            float4 c0 = *(float4*)Crow, c1 = *(float4*)(Crow+4);
            c0.x += acc[i][0]; c0.y += acc[i][1]; c0.z += acc[i][2]; c0.w += acc[i][3];
            c1.x += acc[i][4]; c1.y += acc[i][5]; c1.z += acc[i][6]; c1.w += acc[i][7];
            *(float4*)Crow = c0; *(float4*)(Crow+4) = c1;
        } else {
            float4 c0 = *(float4*)Crow, c1 = *(float4*)(Crow+4);
            c0.x += acc[i][0] + bias[bn+tx*8+0];
            c0.y += acc[i][1] + bias[bn+tx*8+1];
            c0.z += acc[i][2] + bias[bn+tx*8+2];
            c0.w += acc[i][3] + bias[bn+tx*8+3];
            c1.x += acc[i][4] + bias[bn+tx*8+4];
            c1.y += acc[i][5] + bias[bn+tx*8+5];
            c1.z += acc[i][6] + bias[bn+tx*8+6];
            c1.w += acc[i][7] + bias[bn+tx*8+7];
            *(float4*)Crow = c0; *(float4*)(Crow+4) = c1;
        }
    }
}

// ---------------- LSH hashing: rot cached in smem ----------------
__global__ void hash_kernel(const float* __restrict__ rot,
                            const float* __restrict__ qk, int* __restrict__ bkt) {
    __shared__ float rs[DHh*64];
    int tid = threadIdx.x;
    for (int i = tid; i < DHh*64; i += 256) rs[i] = rot[i];
    __syncthreads();
    int idx = blockIdx.x*256 + tid;
    int t  = idx & (Tt-1);
    int nh = (idx >> 10) & 7;
    int bh = idx >> 13;
    int b = bh >> 3, h = bh & 7;
    const float* qrow = &qk[(size_t)(b*Tt + t)*Dd + h*DHh];
    float rv[8];
    #pragma unroll
    for (int r = 0; r < 8; r++) rv[r] = 0.f;
    #pragma unroll 4
    for (int d4 = 0; d4 < 16; d4++) {
        float4 q4 = *(const float4*)(qrow + d4*4);
        float qv[4] = {q4.x, q4.y, q4.z, q4.w};
        #pragma unroll
        for (int e = 0; e < 4; e++) {
            const float* rp = &rs[(d4*4+e)*64 + nh*8];
            #pragma unroll
            for (int r = 0; r < 8; r++) rv[r] += qv[e]*rp[r];
        }
    }
    int best = 0; float bv = rv[0];
    #pragma unroll
    for (int r = 1; r < 8; r++) if (rv[r] > bv) { bv = rv[r]; best = r; }
    #pragma unroll
    for (int r = 0; r < 8; r++) { float nv = -rv[r]; if (nv > bv) { bv = nv; best = 8 + r; } }
    bkt[(bh*NHh + nh)*Tt + t] = best;
}

// ---------------- stable counting sort: one 512-thread block per segment ----------------
__global__ void sort_kernel(const int* __restrict__ bkt, int* __restrict__ st) {
    __shared__ int sb[Tt];
    __shared__ int cnt[16];
    __shared__ int off[16];
    int base = blockIdx.x*Tt;
    int tid = threadIdx.x;
    for (int i = tid; i < Tt; i += 512) sb[i] = bkt[base + i];
    __syncthreads();
    int w = tid >> 5, lane = tid & 31;
    int c = 0;
    for (int it = 0; it < 32; it++) {
        unsigned m = __ballot_sync(0xffffffffu, sb[it*32 + lane] == w);
        c += __popc(m);
    }
    if (lane == 0) cnt[w] = c;
    __syncthreads();
    if (tid == 0) {
        int s = 0;
        for (int i = 0; i < 16; i++) { off[i] = s; s += cnt[i]; }
    }
    __syncthreads();
    int p = off[w];
    for (int it = 0; it < 32; it++) {
        int t = it*32 + lane;
        int bb = sb[t];
        unsigned m = __ballot_sync(0xffffffffu, bb == w);
        if (bb == w) {
            int pos = p + __popc(m & ((1u << lane) - 1u));
            st[base + pos] = t;
        }
        p += __popc(m);
    }
}

// ---------------- chunked LSH attention: register-tiled, one CTA per (chunk, bh) ----------------
__global__ void __launch_bounds__(256) attn_kernel(const int* __restrict__ st,
                                                   const float* __restrict__ qk,
                                                   const float* __restrict__ vg,
                                                   float* __restrict__ slog,
                                                   float* __restrict__ bo) {
    extern __shared__ float sm[];
    float* qs   = sm;                  // [64][65]  q tile / K half0 / V half0
    float* ks   = qs + 64*65;          // [64][65]  K half1 / V half1
    float* sd   = ks + 64*65;          // [64][132] dots -> probs
    float* invs = sd + 64*132;         // [128]
    int*   posK = (int*)(invs + 128);  // [128]

    int n = blockIdx.x, bh = blockIdx.y;
    int b = bh >> 3, h = bh & 7;
    int tid = threadIdx.x;
    int nh = n >> 4;
    int segb = bh*SEG;

    if (tid < 128) {
        int cc = (tid < 64) ? n : ((n + NC - 1) & (NC-1));
        posK[tid] = st[segb + cc*BSz + (tid & 63)];
    }
    __syncthreads();

    // load q tile (= K half0) and K half1, float4 gathers, scalar smem stores
    for (int i = tid; i < 64*16; i += 256) {
        int r = i >> 4, c4 = (i & 15)*4;
        float4 a = *(const float4*)&qk[(size_t)(b*Tt + posK[r])*Dd + h*DHh + c4];
        qs[r*65 + c4+0] = a.x; qs[r*65 + c4+1] = a.y;
        qs[r*65 + c4+2] = a.z; qs[r*65 + c4+3] = a.w;
        float4 k2 = *(const float4*)&qk[(size_t)(b*Tt + posK[64+r])*Dd + h*DHh + c4];
        ks[r*65 + c4+0] = k2.x; ks[r*65 + c4+1] = k2.y;
        ks[r*65 + c4+2] = k2.z; ks[r*65 + c4+3] = k2.w;
    }
    __syncthreads();

    // key inverse norms
    if (tid < 128) {
        const float* kb = (tid < 64) ? qs : ks;
        int r = tid & 63;
        float s = 0.f;
        #pragma unroll 8
        for (int d = 0; d < 64; d++) { float x = kb[r*65 + d]; s += x*x; }
        invs[tid] = 1.f/(sqrtf(s) + 1e-8f);
    }
    __syncthreads();

    // QK^T: 4q x 4k register tile per thread, both halves
    {
        int ty = tid >> 4, tx = tid & 15;
        #pragma unroll
        for (int half = 0; half < 2; half++) {
            const float* kb = half ? ks : qs;
            float acc[4][4];
            #pragma unroll
            for (int i = 0; i < 4; i++)
                #pragma unroll
                for (int j = 0; j < 4; j++) acc[i][j] = 0.f;
            #pragma unroll 4
            for (int d = 0; d < 64; d++) {
                float a0 = qs[(ty*4+0)*65 + d], a1 = qs[(ty*4+1)*65 + d];
                float a2 = qs[(ty*4+2)*65 + d], a3 = qs[(ty*4+3)*65 + d];
                float b0 = kb[(tx*4+0)*65 + d], b1 = kb[(tx*4+1)*65 + d];
                float b2 = kb[(tx*4+2)*65 + d], b3 = kb[(tx*4+3)*65 + d];
                acc[0][0]+=a0*b0; acc[0][1]+=a0*b1; acc[0][2]+=a0*b2; acc[0][3]+=a0*b3;
                acc[1][0]+=a1*b0; acc[1][1]+=a1*b1; acc[1][2]+=a1*b2; acc[1][3]+=a1*b3;
                acc[2][0]+=a2*b0; acc[2][1]+=a2*b1; acc[2][2]+=a2*b2; acc[2][3]+=a2*b3;
                acc[3][0]+=a3*b0; acc[3][1]+=a3*b1; acc[3][2]+=a3*b2; acc[3][3]+=a3*b3;
            }
            #pragma unroll
            for (int i = 0; i < 4; i++) {
                int qr = ty*4 + i, pq = posK[qr];
                #pragma unroll
                for (int j = 0; j < 4; j++) {
                    int kl = tx*4 + j;
                    float s = acc[i][j]*0.125f*invs[half*64 + kl];
                    if (pq == posK[half*64 + kl]) s = -5e4f;
                    sd[qr*132 + half*64 + kl] = s;
                }
            }
        }
    }
    __syncthreads();

    // softmax per row: thread quad (r, c4) covers 32 strided entries
    {
        int r = tid >> 2, c4 = tid & 3;
        float vals[32];
        float mx = -1e30f;
        #pragma unroll
        for (int i = 0; i < 32; i++) { vals[i] = sd[r*132 + i*4 + c4]; mx = fmaxf(mx, vals[i]); }
        mx = fmaxf(mx, __shfl_xor_sync(0xffffffffu, mx, 1));
        mx = fmaxf(mx, __shfl_xor_sync(0xffffffffu, mx, 2));
        float se = 0.f;
        #pragma unroll
        for (int i = 0; i < 32; i++) { vals[i] = __expf(vals[i] - mx); se += vals[i]; }
        se += __shfl_xor_sync(0xffffffffu, se, 1);
        se += __shfl_xor_sync(0xffffffffu, se, 2);
        if (c4 == 0) slog[((size_t)bh*NHh + nh)*Tt + posK[r]] = mx + __logf(se);
        float inv_se = 1.f/se;
        #pragma unroll
        for (int i = 0; i < 32; i++) sd[r*132 + i*4 + c4] = vals[i]*inv_se;
    }
    __syncthreads();

    // load V halves over q/k buffers
    for (int i = tid; i < 64*16; i += 256) {
        int r = i >> 4, c4 = (i & 15)*4;
        float4 a = *(const float4*)&vg[(size_t)(b*Tt + posK[r])*Dd + h*DHh + c4];
        qs[r*65 + c4+0] = a.x; qs[r*65 + c4+1] = a.y;
        qs[r*65 + c4+2] = a.z; qs[r*65 + c4+3] = a.w;
        float4 k2 = *(const float4*)&vg[(size_t)(b*Tt + posK[64+r])*Dd + h*DHh + c4];
        ks[r*65 + c4+0] = k2.x; ks[r*65 + c4+1] = k2.y;
        ks[r*65 + c4+2] = k2.z; ks[r*65 + c4+3] = k2.w;
    }
    __syncthreads();

    // PV: 4q x 4d register tile per thread over 128 keys
    {
        int ty = tid >> 4, tx = tid & 15;
        float acc[4][4];
        #pragma unroll
        for (int i = 0; i < 4; i++)
            #pragma unroll
            for (int j = 0; j < 4; j++) acc[i][j] = 0.f;
        #pragma unroll 4
        for (int k = 0; k < 64; k++) {
            float p0 = sd[(ty*4+0)*132 + k], p1 = sd[(ty*4+1)*132 + k];
            float p2 = sd[(ty*4+2)*132 + k], p3 = sd[(ty*4+3)*132 + k];
            float v0 = qs[k*65 + tx*4+0], v1 = qs[k*65 + tx*4+1];
            float v2 = qs[k*65 + tx*4+2], v3 = qs[k*65 + tx*4+3];
            acc[0][0]+=p0*v0; acc[0][1]+=p0*v1; acc[0][2]+=p0*v2; acc[0][3]+=p0*v3;
            acc[1][0]+=p1*v0; acc[1][1]+=p1*v1; acc[1][2]+=p1*v2; acc[1][3]+=p1*v3;
            acc[2][0]+=p2*v0; acc[2][1]+=p2*v1; acc[2][2]+=p2*v2; acc[2][3]+=p2*v3;
            acc[3][0]+=p3*v0; acc[3][1]+=p3*v1; acc[3][2]+=p3*v2; acc[3][3]+=p3*v3;
        }
        #pragma unroll 4
        for (int k = 0; k < 64; k++) {
            float p0 = sd[(ty*4+0)*132 + 64+k], p1 = sd[(ty*4+1)*132 + 64+k];
            float p2 = sd[(ty*4+2)*132 + 64+k], p3 = sd[(ty*4+3)*132 + 64+k];
            float v0 = ks[k*65 + tx*4+0], v1 = ks[k*65 + tx*4+1];
            float v2 = ks[k*65 + tx*4+2], v3 = ks[k*65 + tx*4+3];
            acc[0][0]+=p0*v0; acc[0][1]+=p0*v1; acc[0][2]+=p0*v2; acc[0][3]+=p0*v3;
            acc[1][0]+=p1*v0; acc[1][1]+=p1*v1; acc[1][2]+=p1*v2; acc[1][3]+=p1*v3;
            acc[2][0]+=p2*v0; acc[2][1]+=p2*v1; acc[2][2]+=p2*v2; acc[2][3]+=p2*v3;
            acc[3][0]+=p3*v0; acc[3][1]+=p3*v1; acc[3][2]+=p3*v2; acc[3][3]+=p3*v3;
        }
        #pragma unroll
        for (int i = 0; i < 4; i++) {
            int qr = ty*4 + i;
            float* bop = &bo[(((size_t)bh*NHh + nh)*Tt + posK[qr])*DHh + tx*4];
            *(float4*)bop = make_float4(acc[i][0], acc[i][1], acc[i][2], acc[i][3]);
        }
    }
}

// ---------------- multi-round logsumexp-weighted combine (float4) ----------------
__global__ void combine_kernel(const float* __restrict__ slog,
                               const float* __restrict__ bo,
                               float* __restrict__ ao) {
    int idx = blockIdx.x*256 + threadIdx.x;
    if (idx >= BHn*Tt*16) return;
    int d4 = (idx & 15)*4;
    int t  = (idx >> 4) & (Tt-1);
    int bh = idx >> 14;
    float lg[NHh];
    float mx = -1e30f;
    #pragma unroll
    for (int i = 0; i < NHh; i++) {
        lg[i] = slog[((size_t)bh*NHh + i)*Tt + t];
        mx = fmaxf(mx, lg[i]);
    }
    float se = 0.f;
    #pragma unroll
    for (int i = 0; i < NHh; i++) { lg[i] = __expf(lg[i] - mx); se += lg[i]; }
    float inv = 1.f/se;
    float4 out = make_float4(0.f, 0.f, 0.f, 0.f);
    #pragma unroll
    for (int i = 0; i < NHh; i++) {
        float w = lg[i]*inv;
        float4 bv = *(const float4*)&bo[(((size_t)bh*NHh + i)*Tt + t)*DHh + d4];
        out.x += w*bv.x; out.y += w*bv.y; out.z += w*bv.z; out.w += w*bv.w;
    }
    int b = bh >> 3, h = bh & 7;
    *(float4*)&ao[(size_t)(b*Tt + t)*Dd + h*DHh + d4] = out;
}

// ---------------- final pooling + fc ----------------
__global__ void pool_kernel(const float* __restrict__ xn, float* __restrict__ pool) {
    int b = blockIdx.x, d = threadIdx.x;
    float s = 0.f;
    for (int t = 0; t < Tt; t++) s += xn[(size_t)(b*Tt + t)*Dd + d];
    pool[b*Dd + d] = s * (1.f/(float)Tt);
}

__global__ void fc_kernel(const float* __restrict__ pool,
                          const float* __restrict__ Wfc, float* __restrict__ out) {
    int b = blockIdx.x, n = threadIdx.x;
    float s = 0.f;
    for (int kk = 0; kk < Dd; kk++) s += pool[b*Dd + kk]*Wfc[kk*Dd + n];
    out[b*Dd + n] = s;
}

// ---------------- orchestration ----------------
extern "C" void kernel_launch(void* const* d_in, const int* in_sizes, int n_in,
                              void* d_out, int out_size) {
    const int*   ids = (const int*)  d_in[0];
    const float* tok = (const float*)d_in[1];
    const float* pos = (const float*)d_in[2];
    const float* lag = (const float*)d_in[3];
    const float* lab = (const float*)d_in[4];
    const float* Wqk = (const float*)d_in[5];
    const float* Wv  = (const float*)d_in[6];
    const float* Wo  = (const float*)d_in[7];
    const float* lfg = (const float*)d_in[8];
    const float* lfb = (const float*)d_in[9];
    const float* W1  = (const float*)d_in[10];
    const float* b1  = (const float*)d_in[11];
    const float* W2  = (const float*)d_in[12];
    const float* b2  = (const float*)d_in[13];
    const float* lng = (const float*)d_in[14];
    const float* lnb = (const float*)d_in[15];
    const float* Wfc = (const float*)d_in[16];
    const float* rot = (const float*)d_in[17];
    float* out = (float*)d_out;

    float *x1, *x2, *xn, *qk, *v, *ao, *ffh, *bo, *slog, *pool;
    int *st, *bkt;
    cudaGetSymbolAddress((void**)&x1,   g_x1);
    cudaGetSymbolAddress((void**)&x2,   g_x2);
    cudaGetSymbolAddress((void**)&xn,   g_xn);
    cudaGetSymbolAddress((void**)&qk,   g_qk);
    cudaGetSymbolAddress((void**)&v,    g_v);
    cudaGetSymbolAddress((void**)&ao,   g_ao);
    cudaGetSymbolAddress((void**)&ffh,  g_ffh);
    cudaGetSymbolAddress((void**)&bo,   g_bo);
    cudaGetSymbolAddress((void**)&slog, g_slog);
    cudaGetSymbolAddress((void**)&pool, g_pool);
    cudaGetSymbolAddress((void**)&st,   g_st);
    cudaGetSymbolAddress((void**)&bkt,  g_bkt);

    const int ATTN_SMEM = (64*65 + 64*65 + 64*132 + 128)*4 + 128*4;
    cudaFuncSetAttribute(attn_kernel, cudaFuncAttributeMaxDynamicSharedMemorySize, ATTN_SMEM);

    const int M = Bb*Tt;

    embed_kernel<<<(Bb*Tt*Dd + 255)/256, 256>>>(ids, tok, pos, x1, x2);

    for (int l = 0; l < DEPTHL; l++) {
        const float* Wqk_l = Wqk + (size_t)l*Dd*Dd;
        const float* Wv_l  = Wv  + (size_t)l*Dd*Dd;
        const float* Wo_l  = Wo  + (size_t)l*Dd*Dd;
        const float* W1_l  = W1  + (size_t)l*Dd*FFf;
        const float* W2_l  = W2  + (size_t)l*FFf*Dd;
        const float* b1_l  = b1  + (size_t)l*FFf;
        const float* b2_l  = b2  + (size_t)l*Dd;
        const float* rot_l = rot + (size_t)l*DHh*64;

        // attention block: x1 += attn(LN(x2)) @ Wo
        ln_kernel<<<M, 256>>>(x2, nullptr, xn, lag + l*Dd, lab + l*Dd);
        gemm_kernel<0><<<dim3(Dd/128, M/128), 256>>>(xn, Wqk_l, nullptr, qk, M, Dd, Dd);
        gemm_kernel<0><<<dim3(Dd/128, M/128), 256>>>(xn, Wv_l,  nullptr, v,  M, Dd, Dd);
        hash_kernel<<<(BHn*NHh*Tt)/256, 256>>>(rot_l, qk, bkt);
        sort_kernel<<<BHn*NHh, 512>>>(bkt, st);
        attn_kernel<<<dim3(NC, BHn), 256, ATTN_SMEM>>>(st, qk, v, slog, bo);
        combine_kernel<<<(BHn*Tt*16)/256, 256>>>(slog, bo, ao);
        gemm_kernel<3><<<dim3(Dd/128, M/128), 256>>>(ao, Wo_l, nullptr, x1, M, Dd, Dd);

        // feed-forward block: x2 += gelu(LN(x1)@W1 + b1) @ W2 + b2
        ln_kernel<<<M, 256>>>(x1, nullptr, xn, lfg + l*Dd, lfb + l*Dd);
        gemm_kernel<1><<<dim3(FFf/128, M/128), 256>>>(xn, W1_l, b1_l, ffh, M, FFf, Dd);
        gemm_kernel<4><<<dim3(Dd/128, M/128), 256>>>(ffh, W2_l, b2_l, x2, M, Dd, FFf);
    }

    // final: 0.5*(x1+x2) -> LN -> mean over T -> @ Wfc
    ln_kernel<<<M, 256>>>(x1, x2, xn, lng, lnb);
    pool_kernel<<<Bb, Dd>>>(xn, pool);
    fc_kernel<<<Bb, Dd>>>(pool, Wfc, out);
}

// round 10
// speedup vs baseline: 2.3937x; 1.1231x over previous
#include <cuda_runtime.h>
#include <math.h>
#include <stdint.h>

#define Bb 8
#define Tt 1024
#define Dd 512
#define Hh 8
#define DHh 64
#define DEPTHL 8
#define FFf 2048
#define NHh 8
#define BSz 64
#define NBk 16
#define NC (NHh*NBk)
#define BHn (Bb*Hh)
#define SEG (NHh*Tt)

// ---------------- scratch (device symbols; addresses resolved on host) ----------------
__device__ float g_x1[Bb*Tt*Dd];
__device__ float g_x2[Bb*Tt*Dd];
__device__ float g_xn[Bb*Tt*Dd];
__device__ float g_qk[Bb*Tt*Dd];
__device__ float g_v [Bb*Tt*Dd];
__device__ float g_ao[Bb*Tt*Dd];
__device__ float g_ffh[Bb*Tt*FFf];
__device__ float g_bo[(size_t)BHn*NHh*Tt*DHh];
__device__ float g_slog[BHn*NHh*Tt];
__device__ int   g_st [BHn*SEG];
__device__ int   g_bkt[BHn*SEG];
__device__ float g_pool[Bb*Dd];

// ---------------- helpers ----------------
__device__ __forceinline__ float gelu_fast(float x) {
    float u = 0.7978845608028654f*(x + 0.044715f*x*x*x);
    float t = 1.f - 2.f/(__expf(2.f*u) + 1.f);
    return 0.5f*x*(1.f + t);
}

__device__ __forceinline__ float blockReduceSum256(float val, float* red) {
    #pragma unroll
    for (int o = 16; o; o >>= 1) val += __shfl_xor_sync(0xffffffffu, val, o);
    int w = threadIdx.x >> 5;
    if ((threadIdx.x & 31) == 0) red[w] = val;
    __syncthreads();
    float r = (threadIdx.x < 8) ? red[threadIdx.x] : 0.f;
    if (threadIdx.x < 32) {
        #pragma unroll
        for (int o = 4; o; o >>= 1) r += __shfl_xor_sync(0xffffffffu, r, o);
        if (threadIdx.x == 0) red[0] = r;
    }
    __syncthreads();
    float out = red[0];
    __syncthreads();
    return out;
}

__device__ __forceinline__ unsigned f2tf32(float x) {
    unsigned r;
    asm("cvt.rna.tf32.f32 %0, %1;" : "=r"(r) : "f"(x));
    return r;
}

__device__ __forceinline__ void mma_tf32(float* c,
    unsigned a0, unsigned a1, unsigned a2, unsigned a3,
    unsigned b0, unsigned b1) {
    asm volatile(
        "mma.sync.aligned.m16n8k8.row.col.f32.tf32.tf32.f32 "
        "{%0,%1,%2,%3}, {%4,%5,%6,%7}, {%8,%9}, {%0,%1,%2,%3};"
        : "+f"(c[0]), "+f"(c[1]), "+f"(c[2]), "+f"(c[3])
        : "r"(a0), "r"(a1), "r"(a2), "r"(a3), "r"(b0), "r"(b1));
}

// ---------------- embedding ----------------
__global__ void embed_kernel(const int* __restrict__ ids,
                             const float* __restrict__ tok,
                             const float* __restrict__ pos,
                             float* __restrict__ x1, float* __restrict__ x2) {
    int i = blockIdx.x*256 + threadIdx.x;
    if (i >= Bb*Tt*Dd) return;
    int d = i & (Dd-1);
    int bt = i >> 9;
    int t = bt & (Tt-1);
    int id = ids[bt];
    if (id < 0) id = 0;
    if (id >= 6400) id = 6399;
    float v = tok[(size_t)id*Dd + d] + pos[t*Dd + d];
    x1[i] = v; x2[i] = v;
}

// ---------------- layernorm ----------------
__global__ void ln_kernel(const float* __restrict__ x, const float* __restrict__ xb,
                          float* __restrict__ y,
                          const float* __restrict__ g, const float* __restrict__ bia) {
    __shared__ float red[8];
    int row = blockIdx.x;
    int i0 = row*Dd + threadIdx.x;
    float v0, v1;
    if (xb) { v0 = 0.5f*(x[i0] + xb[i0]); v1 = 0.5f*(x[i0+256] + xb[i0+256]); }
    else    { v0 = x[i0];                 v1 = x[i0+256]; }
    float s = blockReduceSum256(v0+v1, red);
    float mean = s * (1.f/512.f);
    float d0 = v0 - mean, d1 = v1 - mean;
    float s2 = blockReduceSum256(d0*d0 + d1*d1, red);
    float inv = rsqrtf(s2*(1.f/512.f) + 1e-5f);
    y[i0]     = d0*inv*g[threadIdx.x]     + bia[threadIdx.x];
    y[i0+256] = d1*inv*g[threadIdx.x+256] + bia[threadIdx.x+256];
}

// ---------------- tensor-core GEMM (3xTF32): C = A[MxK] @ B[KxN] ----------------
// 128x128 tile, BK=16, 8 warps (2m x 4n), warp tile 64x32.
// EPI: 0 = store, 1 = gelu(acc+bias) store, 3 = C += acc, 4 = C += acc + bias
template<int EPI>
__global__ void __launch_bounds__(256) gemm_kernel(const float* __restrict__ A,
                            const float* __restrict__ Bm,
                            const float* __restrict__ bias, float* __restrict__ C,
                            int M, int N, int K) {
    __shared__ float As[16][136];
    __shared__ float Bs[16][136];
    const int tid  = threadIdx.x;
    const int lane = tid & 31;
    const int warp = tid >> 5;
    const int wm = warp & 1;          // 0..1  (64 rows each)
    const int wn = warp >> 1;         // 0..3  (32 cols each)
    const int gid = lane >> 2;        // 0..7
    const int qid = lane & 3;         // 0..3
    const int bm = blockIdx.y*128, bn = blockIdx.x*128;

    float c[4][4][4];
    #pragma unroll
    for (int mt = 0; mt < 4; mt++)
        #pragma unroll
        for (int nt = 0; nt < 4; nt++)
            #pragma unroll
            for (int e = 0; e < 4; e++) c[mt][nt][e] = 0.f;

    // global-load coordinates
    const int aR  = (tid + 0)   >> 2, aK  = ((tid + 0)   & 3)*4;
    const int aR2 = (tid + 256) >> 2, aK2 = ((tid + 256) & 3)*4;
    const int bK  = (tid + 0)   >> 5, bN  = ((tid + 0)   & 31)*4;
    const int bK2 = (tid + 256) >> 5, bN2 = ((tid + 256) & 31)*4;

    const int nk = K >> 4;

    // preload tile 0
    {
        float4 v0 = *(const float4*)(A + (size_t)(bm + aR)*K + aK);
        float4 v1 = *(const float4*)(A + (size_t)(bm + aR2)*K + aK2);
        As[aK+0][aR]  = v0.x; As[aK+1][aR]  = v0.y; As[aK+2][aR]  = v0.z; As[aK+3][aR]  = v0.w;
        As[aK2+0][aR2]= v1.x; As[aK2+1][aR2]= v1.y; As[aK2+2][aR2]= v1.z; As[aK2+3][aR2]= v1.w;
        *(float4*)&Bs[bK][bN]   = *(const float4*)(Bm + (size_t)bK*N  + bn + bN);
        *(float4*)&Bs[bK2][bN2] = *(const float4*)(Bm + (size_t)bK2*N + bn + bN2);
    }
    __syncthreads();

    for (int kt = 0; kt < nk; kt++) {
        float4 pa0, pa1, pb0, pb1;
        if (kt + 1 < nk) {
            int k0 = (kt + 1)*16;
            pa0 = *(const float4*)(A + (size_t)(bm + aR)*K  + k0 + aK);
            pa1 = *(const float4*)(A + (size_t)(bm + aR2)*K + k0 + aK2);
            pb0 = *(const float4*)(Bm + (size_t)(k0 + bK)*N  + bn + bN);
            pb1 = *(const float4*)(Bm + (size_t)(k0 + bK2)*N + bn + bN2);
        }

        #pragma unroll
        for (int ks = 0; ks < 2; ks++) {
            const int k0 = ks*8;
            unsigned ahi[4][4], alo[4][4];
            #pragma unroll
            for (int mt = 0; mt < 4; mt++) {
                int mc = wm*64 + mt*16;
                float x0 = As[k0+qid  ][mc+gid];
                float x1 = As[k0+qid  ][mc+gid+8];
                float x2 = As[k0+qid+4][mc+gid];
                float x3 = As[k0+qid+4][mc+gid+8];
                ahi[mt][0] = f2tf32(x0); alo[mt][0] = f2tf32(x0 - __uint_as_float(ahi[mt][0]));
                ahi[mt][1] = f2tf32(x1); alo[mt][1] = f2tf32(x1 - __uint_as_float(ahi[mt][1]));
                ahi[mt][2] = f2tf32(x2); alo[mt][2] = f2tf32(x2 - __uint_as_float(ahi[mt][2]));
                ahi[mt][3] = f2tf32(x3); alo[mt][3] = f2tf32(x3 - __uint_as_float(ahi[mt][3]));
            }
            #pragma unroll
            for (int nt = 0; nt < 4; nt++) {
                int nc = wn*32 + nt*8;
                float y0 = Bs[k0+qid  ][nc+gid];
                float y1 = Bs[k0+qid+4][nc+gid];
                unsigned bh0 = f2tf32(y0), bl0 = f2tf32(y0 - __uint_as_float(bh0));
                unsigned bh1 = f2tf32(y1), bl1 = f2tf32(y1 - __uint_as_float(bh1));
                #pragma unroll
                for (int mt = 0; mt < 4; mt++) {
                    mma_tf32(c[mt][nt], ahi[mt][0],ahi[mt][1],ahi[mt][2],ahi[mt][3], bh0, bh1);
                    mma_tf32(c[mt][nt], ahi[mt][0],ahi[mt][1],ahi[mt][2],ahi[mt][3], bl0, bl1);
                    mma_tf32(c[mt][nt], alo[mt][0],alo[mt][1],alo[mt][2],alo[mt][3], bh0, bh1);
                }
            }
        }
        __syncthreads();
        if (kt + 1 < nk) {
            As[aK+0][aR]  = pa0.x; As[aK+1][aR]  = pa0.y; As[aK+2][aR]  = pa0.z; As[aK+3][aR]  = pa0.w;
            As[aK2+0][aR2]= pa1.x; As[aK2+1][aR2]= pa1.y; As[aK2+2][aR2]= pa1.z; As[aK2+3][aR2]= pa1.w;
            *(float4*)&Bs[bK][bN]   = pb0;
            *(float4*)&Bs[bK2][bN2] = pb1;
        }
        __syncthreads();
    }

    // epilogue: each c-frag covers rows {r, r+8}, cols {col, col+1}
    #pragma unroll
    for (int mt = 0; mt < 4; mt++) {
        #pragma unroll
        for (int nt = 0; nt < 4; nt++) {
            int row = bm + wm*64 + mt*16 + gid;
            int col = bn + wn*32 + nt*8 + qid*2;
            float* p0 = C + (size_t)row*N + col;
            float* p1 = C + (size_t)(row+8)*N + col;
            float v00 = c[mt][nt][0], v01 = c[mt][nt][1];
            float v10 = c[mt][nt][2], v11 = c[mt][nt][3];
            if (EPI == 0) {
                p0[0] = v00; p0[1] = v01; p1[0] = v10; p1[1] = v11;
            } else if (EPI == 1) {
                float b0v = bias[col], b1v = bias[col+1];
                p0[0] = gelu_fast(v00 + b0v); p0[1] = gelu_fast(v01 + b1v);
                p1[0] = gelu_fast(v10 + b0v); p1[1] = gelu_fast(v11 + b1v);
            } else if (EPI == 3) {
                p0[0] += v00; p0[1] += v01; p1[0] += v10; p1[1] += v11;
            } else {
                float b0v = bias[col], b1v = bias[col+1];
                p0[0] += v00 + b0v; p0[1] += v01 + b1v;
                p1[0] += v10 + b0v; p1[1] += v11 + b1v;
            }
        }
    }
}

// ---------------- LSH hashing: rot cached in smem ----------------
__global__ void hash_kernel(const float* __restrict__ rot,
                            const float* __restrict__ qk, int* __restrict__ bkt) {
    __shared__ float rs[DHh*64];
    int tid = threadIdx.x;
    for (int i = tid; i < DHh*64; i += 256) rs[i] = rot[i];
    __syncthreads();
    int idx = blockIdx.x*256 + tid;
    int t  = idx & (Tt-1);
    int nh = (idx >> 10) & 7;
    int bh = idx >> 13;
    int b = bh >> 3, h = bh & 7;
    const float* qrow = &qk[(size_t)(b*Tt + t)*Dd + h*DHh];
    float rv[8];
    #pragma unroll
    for (int r = 0; r < 8; r++) rv[r] = 0.f;
    #pragma unroll 4
    for (int d4 = 0; d4 < 16; d4++) {
        float4 q4 = *(const float4*)(qrow + d4*4);
        float qv[4] = {q4.x, q4.y, q4.z, q4.w};
        #pragma unroll
        for (int e = 0; e < 4; e++) {
            const float* rp = &rs[(d4*4+e)*64 + nh*8];
            #pragma unroll
            for (int r = 0; r < 8; r++) rv[r] += qv[e]*rp[r];
        }
    }
    int best = 0; float bv = rv[0];
    #pragma unroll
    for (int r = 1; r < 8; r++) if (rv[r] > bv) { bv = rv[r]; best = r; }
    #pragma unroll
    for (int r = 0; r < 8; r++) { float nv = -rv[r]; if (nv > bv) { bv = nv; best = 8 + r; } }
    bkt[(bh*NHh + nh)*Tt + t] = best;
}

// ---------------- stable counting sort ----------------
__global__ void sort_kernel(const int* __restrict__ bkt, int* __restrict__ st) {
    __shared__ int sb[Tt];
    __shared__ int cnt[16];
    __shared__ int off[16];
    int base = blockIdx.x*Tt;
    int tid = threadIdx.x;
    for (int i = tid; i < Tt; i += 512) sb[i] = bkt[base + i];
    __syncthreads();
    int w = tid >> 5, lane = tid & 31;
    int c = 0;
    for (int it = 0; it < 32; it++) {
        unsigned m = __ballot_sync(0xffffffffu, sb[it*32 + lane] == w);
        c += __popc(m);
    }
    if (lane == 0) cnt[w] = c;
    __syncthreads();
    if (tid == 0) {
        int s = 0;
        for (int i = 0; i < 16; i++) { off[i] = s; s += cnt[i]; }
    }
    __syncthreads();
    int p = off[w];
    for (int it = 0; it < 32; it++) {
        int t = it*32 + lane;
        int bb = sb[t];
        unsigned m = __ballot_sync(0xffffffffu, bb == w);
        if (bb == w) {
            int pos = p + __popc(m & ((1u << lane) - 1u));
            st[base + pos] = t;
        }
        p += __popc(m);
    }
}

// ---------------- chunked LSH attention ----------------
__global__ void __launch_bounds__(256) attn_kernel(const int* __restrict__ st,
                                                   const float* __restrict__ qk,
                                                   const float* __restrict__ vg,
                                                   float* __restrict__ slog,
                                                   float* __restrict__ bo) {
    extern __shared__ float sm[];
    float* qs   = sm;
    float* ks   = qs + 64*65;
    float* sd   = ks + 64*65;
    float* invs = sd + 64*132;
    int*   posK = (int*)(invs + 128);

    int n = blockIdx.x, bh = blockIdx.y;
    int b = bh >> 3, h = bh & 7;
    int tid = threadIdx.x;
    int nh = n >> 4;
    int segb = bh*SEG;

    if (tid < 128) {
        int cc = (tid < 64) ? n : ((n + NC - 1) & (NC-1));
        posK[tid] = st[segb + cc*BSz + (tid & 63)];
    }
    __syncthreads();

    for (int i = tid; i < 64*16; i += 256) {
        int r = i >> 4, c4 = (i & 15)*4;
        float4 a = *(const float4*)&qk[(size_t)(b*Tt + posK[r])*Dd + h*DHh + c4];
        qs[r*65 + c4+0] = a.x; qs[r*65 + c4+1] = a.y;
        qs[r*65 + c4+2] = a.z; qs[r*65 + c4+3] = a.w;
        float4 k2 = *(const float4*)&qk[(size_t)(b*Tt + posK[64+r])*Dd + h*DHh + c4];
        ks[r*65 + c4+0] = k2.x; ks[r*65 + c4+1] = k2.y;
        ks[r*65 + c4+2] = k2.z; ks[r*65 + c4+3] = k2.w;
    }
    __syncthreads();

    if (tid < 128) {
        const float* kb = (tid < 64) ? qs : ks;
        int r = tid & 63;
        float s = 0.f;
        #pragma unroll 8
        for (int d = 0; d < 64; d++) { float x = kb[r*65 + d]; s += x*x; }
        invs[tid] = 1.f/(sqrtf(s) + 1e-8f);
    }
    __syncthreads();

    {
        int ty = tid >> 4, tx = tid & 15;
        #pragma unroll
        for (int half = 0; half < 2; half++) {
            const float* kb = half ? ks : qs;
            float acc[4][4];
            #pragma unroll
            for (int i = 0; i < 4; i++)
                #pragma unroll
                for (int j = 0; j < 4; j++) acc[i][j] = 0.f;
            #pragma unroll 4
            for (int d = 0; d < 64; d++) {
                float a0 = qs[(ty*4+0)*65 + d], a1 = qs[(ty*4+1)*65 + d];
                float a2 = qs[(ty*4+2)*65 + d], a3 = qs[(ty*4+3)*65 + d];
                float b0 = kb[(tx*4+0)*65 + d], b1 = kb[(tx*4+1)*65 + d];
                float b2 = kb[(tx*4+2)*65 + d], b3 = kb[(tx*4+3)*65 + d];
                acc[0][0]+=a0*b0; acc[0][1]+=a0*b1; acc[0][2]+=a0*b2; acc[0][3]+=a0*b3;
                acc[1][0]+=a1*b0; acc[1][1]+=a1*b1; acc[1][2]+=a1*b2; acc[1][3]+=a1*b3;
                acc[2][0]+=a2*b0; acc[2][1]+=a2*b1; acc[2][2]+=a2*b2; acc[2][3]+=a2*b3;
                acc[3][0]+=a3*b0; acc[3][1]+=a3*b1; acc[3][2]+=a3*b2; acc[3][3]+=a3*b3;
            }
            #pragma unroll
            for (int i = 0; i < 4; i++) {
                int qr = ty*4 + i, pq = posK[qr];
                #pragma unroll
                for (int j = 0; j < 4; j++) {
                    int kl = tx*4 + j;
                    float s = acc[i][j]*0.125f*invs[half*64 + kl];
                    if (pq == posK[half*64 + kl]) s = -5e4f;
                    sd[qr*132 + half*64 + kl] = s;
                }
            }
        }
    }
    __syncthreads();

    {
        int r = tid >> 2, c4 = tid & 3;
        float vals[32];
        float mx = -1e30f;
        #pragma unroll
        for (int i = 0; i < 32; i++) { vals[i] = sd[r*132 + i*4 + c4]; mx = fmaxf(mx, vals[i]); }
        mx = fmaxf(mx, __shfl_xor_sync(0xffffffffu, mx, 1));
        mx = fmaxf(mx, __shfl_xor_sync(0xffffffffu, mx, 2));
        float se = 0.f;
        #pragma unroll
        for (int i = 0; i < 32; i++) { vals[i] = __expf(vals[i] - mx); se += vals[i]; }
        se += __shfl_xor_sync(0xffffffffu, se, 1);
        se += __shfl_xor_sync(0xffffffffu, se, 2);
        if (c4 == 0) slog[((size_t)bh*NHh + nh)*Tt + posK[r]] = mx + __logf(se);
        float inv_se = 1.f/se;
        #pragma unroll
        for (int i = 0; i < 32; i++) sd[r*132 + i*4 + c4] = vals[i]*inv_se;
    }
    __syncthreads();

    for (int i = tid; i < 64*16; i += 256) {
        int r = i >> 4, c4 = (i & 15)*4;
        float4 a = *(const float4*)&vg[(size_t)(b*Tt + posK[r])*Dd + h*DHh + c4];
        qs[r*65 + c4+0] = a.x; qs[r*65 + c4+1] = a.y;
        qs[r*65 + c4+2] = a.z; qs[r*65 + c4+3] = a.w;
        float4 k2 = *(const float4*)&vg[(size_t)(b*Tt + posK[64+r])*Dd + h*DHh + c4];
        ks[r*65 + c4+0] = k2.x; ks[r*65 + c4+1] = k2.y;
        ks[r*65 + c4+2] = k2.z; ks[r*65 + c4+3] = k2.w;
    }
    __syncthreads();

    {
        int ty = tid >> 4, tx = tid & 15;
        float acc[4][4];
        #pragma unroll
        for (int i = 0; i < 4; i++)
            #pragma unroll
            for (int j = 0; j < 4; j++) acc[i][j] = 0.f;
        #pragma unroll 4
        for (int k = 0; k < 64; k++) {
            float p0 = sd[(ty*4+0)*132 + k], p1 = sd[(ty*4+1)*132 + k];
            float p2 = sd[(ty*4+2)*132 + k], p3 = sd[(ty*4+3)*132 + k];
            float v0 = qs[k*65 + tx*4+0], v1 = qs[k*65 + tx*4+1];
            float v2 = qs[k*65 + tx*4+2], v3 = qs[k*65 + tx*4+3];
            acc[0][0]+=p0*v0; acc[0][1]+=p0*v1; acc[0][2]+=p0*v2; acc[0][3]+=p0*v3;
            acc[1][0]+=p1*v0; acc[1][1]+=p1*v1; acc[1][2]+=p1*v2; acc[1][3]+=p1*v3;
            acc[2][0]+=p2*v0; acc[2][1]+=p2*v1; acc[2][2]+=p2*v2; acc[2][3]+=p2*v3;
            acc[3][0]+=p3*v0; acc[3][1]+=p3*v1; acc[3][2]+=p3*v2; acc[3][3]+=p3*v3;
        }
        #pragma unroll 4
        for (int k = 0; k < 64; k++) {
            float p0 = sd[(ty*4+0)*132 + 64+k], p1 = sd[(ty*4+1)*132 + 64+k];
            float p2 = sd[(ty*4+2)*132 + 64+k], p3 = sd[(ty*4+3)*132 + 64+k];
            float v0 = ks[k*65 + tx*4+0], v1 = ks[k*65 + tx*4+1];
            float v2 = ks[k*65 + tx*4+2], v3 = ks[k*65 + tx*4+3];
            acc[0][0]+=p0*v0; acc[0][1]+=p0*v1; acc[0][2]+=p0*v2; acc[0][3]+=p0*v3;
            acc[1][0]+=p1*v0; acc[1][1]+=p1*v1; acc[1][2]+=p1*v2; acc[1][3]+=p1*v3;
            acc[2][0]+=p2*v0; acc[2][1]+=p2*v1; acc[2][2]+=p2*v2; acc[2][3]+=p2*v3;
            acc[3][0]+=p3*v0; acc[3][1]+=p3*v1; acc[3][2]+=p3*v2; acc[3][3]+=p3*v3;
        }
        #pragma unroll
        for (int i = 0; i < 4; i++) {
            int qr = ty*4 + i;
            float* bop = &bo[(((size_t)bh*NHh + nh)*Tt + posK[qr])*DHh + tx*4];
            *(float4*)bop = make_float4(acc[i][0], acc[i][1], acc[i][2], acc[i][3]);
        }
    }
}

// ---------------- combine ----------------
__global__ void combine_kernel(const float* __restrict__ slog,
                               const float* __restrict__ bo,
                               float* __restrict__ ao) {
    int idx = blockIdx.x*256 + threadIdx.x;
    if (idx >= BHn*Tt*16) return;
    int d4 = (idx & 15)*4;
    int t  = (idx >> 4) & (Tt-1);
    int bh = idx >> 14;
    float lg[NHh];
    float mx = -1e30f;
    #pragma unroll
    for (int i = 0; i < NHh; i++) {
        lg[i] = slog[((size_t)bh*NHh + i)*Tt + t];
        mx = fmaxf(mx, lg[i]);
    }
    float se = 0.f;
    #pragma unroll
    for (int i = 0; i < NHh; i++) { lg[i] = __expf(lg[i] - mx); se += lg[i]; }
    float inv = 1.f/se;
    float4 out = make_float4(0.f, 0.f, 0.f, 0.f);
    #pragma unroll
    for (int i = 0; i < NHh; i++) {
        float w = lg[i]*inv;
        float4 bv = *(const float4*)&bo[(((size_t)bh*NHh + i)*Tt + t)*DHh + d4];
        out.x += w*bv.x; out.y += w*bv.y; out.z += w*bv.z; out.w += w*bv.w;
    }
    int b = bh >> 3, h = bh & 7;
    *(float4*)&ao[(size_t)(b*Tt + t)*Dd + h*DHh + d4] = out;
}

// ---------------- pooling + fc ----------------
__global__ void pool_kernel(const float* __restrict__ xn, float* __restrict__ pool) {
    int b = blockIdx.x, d = threadIdx.x;
    float s = 0.f;
    for (int t = 0; t < Tt; t++) s += xn[(size_t)(b*Tt + t)*Dd + d];
    pool[b*Dd + d] = s * (1.f/(float)Tt);
}

__global__ void fc_kernel(const float* __restrict__ pool,
                          const float* __restrict__ Wfc, float* __restrict__ out) {
    int b = blockIdx.x, n = threadIdx.x;
    float s = 0.f;
    for (int kk = 0; kk < Dd; kk++) s += pool[b*Dd + kk]*Wfc[kk*Dd + n];
    out[b*Dd + n] = s;
}

// ---------------- orchestration ----------------
extern "C" void kernel_launch(void* const* d_in, const int* in_sizes, int n_in,
                              void* d_out, int out_size) {
    const int*   ids = (const int*)  d_in[0];
    const float* tok = (const float*)d_in[1];
    const float* pos = (const float*)d_in[2];
    const float* lag = (const float*)d_in[3];
    const float* lab = (const float*)d_in[4];
    const float* Wqk = (const float*)d_in[5];
    const float* Wv  = (const float*)d_in[6];
    const float* Wo  = (const float*)d_in[7];
    const float* lfg = (const float*)d_in[8];
    const float* lfb = (const float*)d_in[9];
    const float* W1  = (const float*)d_in[10];
    const float* b1  = (const float*)d_in[11];
    const float* W2  = (const float*)d_in[12];
    const float* b2  = (const float*)d_in[13];
    const float* lng = (const float*)d_in[14];
    const float* lnb = (const float*)d_in[15];
    const float* Wfc = (const float*)d_in[16];
    const float* rot = (const float*)d_in[17];
    float* out = (float*)d_out;

    float *x1, *x2, *xn, *qk, *v, *ao, *ffh, *bo, *slog, *pool;
    int *st, *bkt;
    cudaGetSymbolAddress((void**)&x1,   g_x1);
    cudaGetSymbolAddress((void**)&x2,   g_x2);
    cudaGetSymbolAddress((void**)&xn,   g_xn);
    cudaGetSymbolAddress((void**)&qk,   g_qk);
    cudaGetSymbolAddress((void**)&v,    g_v);
    cudaGetSymbolAddress((void**)&ao,   g_ao);
    cudaGetSymbolAddress((void**)&ffh,  g_ffh);
    cudaGetSymbolAddress((void**)&bo,   g_bo);
    cudaGetSymbolAddress((void**)&slog, g_slog);
    cudaGetSymbolAddress((void**)&pool, g_pool);
    cudaGetSymbolAddress((void**)&st,   g_st);
    cudaGetSymbolAddress((void**)&bkt,  g_bkt);

    const int ATTN_SMEM = (64*65 + 64*65 + 64*132 + 128)*4 + 128*4;
    cudaFuncSetAttribute(attn_kernel, cudaFuncAttributeMaxDynamicSharedMemorySize, ATTN_SMEM);

    const int M = Bb*Tt;

    embed_kernel<<<(Bb*Tt*Dd + 255)/256, 256>>>(ids, tok, pos, x1, x2);

    for (int l = 0; l < DEPTHL; l++) {
        const float* Wqk_l = Wqk + (size_t)l*Dd*Dd;
        const float* Wv_l  = Wv  + (size_t)l*Dd*Dd;
        const float* Wo_l  = Wo  + (size_t)l*Dd*Dd;
        const float* W1_l  = W1  + (size_t)l*Dd*FFf;
        const float* W2_l  = W2  + (size_t)l*FFf*Dd;
        const float* b1_l  = b1  + (size_t)l*FFf;
        const float* b2_l  = b2  + (size_t)l*Dd;
        const float* rot_l = rot + (size_t)l*DHh*64;

        // attention block: x1 += attn(LN(x2)) @ Wo
        ln_kernel<<<M, 256>>>(x2, nullptr, xn, lag + l*Dd, lab + l*Dd);
        gemm_kernel<0><<<dim3(Dd/128, M/128), 256>>>(xn, Wqk_l, nullptr, qk, M, Dd, Dd);
        gemm_kernel<0><<<dim3(Dd/128, M/128), 256>>>(xn, Wv_l,  nullptr, v,  M, Dd, Dd);
        hash_kernel<<<(BHn*NHh*Tt)/256, 256>>>(rot_l, qk, bkt);
        sort_kernel<<<BHn*NHh, 512>>>(bkt, st);
        attn_kernel<<<dim3(NC, BHn), 256, ATTN_SMEM>>>(st, qk, v, slog, bo);
        combine_kernel<<<(BHn*Tt*16)/256, 256>>>(slog, bo, ao);
        gemm_kernel<3><<<dim3(Dd/128, M/128), 256>>>(ao, Wo_l, nullptr, x1, M, Dd, Dd);

        // feed-forward block: x2 += gelu(LN(x1)@W1 + b1) @ W2 + b2
        ln_kernel<<<M, 256>>>(x1, nullptr, xn, lfg + l*Dd, lfb + l*Dd);
        gemm_kernel<1><<<dim3(FFf/128, M/128), 256>>>(xn, W1_l, b1_l, ffh, M, FFf, Dd);
        gemm_kernel<4><<<dim3(Dd/128, M/128), 256>>>(ffh, W2_l, b2_l, x2, M, Dd, FFf);
    }

    // final: 0.5*(x1+x2) -> LN -> mean over T -> @ Wfc
    ln_kernel<<<M, 256>>>(x1, x2, xn, lng, lnb);
    pool_kernel<<<Bb, Dd>>>(xn, pool);
    fc_kernel<<<Bb, Dd>>>(pool, Wfc, out);
}